// round 4
// baseline (speedup 1.0000x reference)
#include <cuda_runtime.h>
#include <float.h>

// Chamfer distance, B=4, N=M=4096, D=3 — fused, S=2 src points per thread.
// dist(p,g) = ||p||^2 + ||g||^2 - 2 p.g ; inner loop per dst point g:
//   1x LDS.128 (g.xyz + ||g||^2), then for BOTH src points: 3 FFMA + 1 FMNMX.
// Halves shared-memory traffic per pair vs 1-src-per-thread (LDS-bound in R3).
// ||p||^2 added after the min. Last CTA finalizes (deterministic fixed-order).

#define BATCH 4
#define NPTS  4096
#define TPB   128
#define SRC_PER_CTA (TPB * 2)            // 256
#define CHUNKS (NPTS / SRC_PER_CTA)      // 16
#define NCTAS (CHUNKS * BATCH * 2)       // 128 CTAs

__device__ float g_partials[NCTAS];
__device__ unsigned int g_count = 0;

__global__ void __launch_bounds__(TPB) chamfer_fused_kernel(
    const float* __restrict__ recon,
    const float* __restrict__ gt,
    float* __restrict__ out)
{
    extern __shared__ float4 sdst[];   // 4096 x float4 = 64 KB

    const int bx  = blockIdx.x;   // src chunk
    const int b   = blockIdx.y;   // batch
    const int dir = blockIdx.z;   // 0: recon->gt, 1: gt->recon
    const int tid = threadIdx.x;

    const float* src = (dir == 0) ? recon : gt;
    const float* dst = (dir == 0) ? gt : recon;
    const float* dstb = dst + (size_t)b * NPTS * 3;

    // Prologue: cache opposite set (+ squared norm) in shared memory.
    for (int base = 4 * tid; base < NPTS; base += 4 * TPB) {
        const float4* gp = (const float4*)(dstb + 3 * base);
        float4 f0 = gp[0];   // x0 y0 z0 x1
        float4 f1 = gp[1];   // y1 z1 x2 y2
        float4 f2 = gp[2];   // z2 x3 y3 z3
        sdst[base + 0] = make_float4(f0.x, f0.y, f0.z,
                                     fmaf(f0.x, f0.x, fmaf(f0.y, f0.y, f0.z * f0.z)));
        sdst[base + 1] = make_float4(f0.w, f1.x, f1.y,
                                     fmaf(f0.w, f0.w, fmaf(f1.x, f1.x, f1.y * f1.y)));
        sdst[base + 2] = make_float4(f1.z, f1.w, f2.x,
                                     fmaf(f1.z, f1.z, fmaf(f1.w, f1.w, f2.x * f2.x)));
        sdst[base + 3] = make_float4(f2.y, f2.z, f2.w,
                                     fmaf(f2.y, f2.y, fmaf(f2.z, f2.z, f2.w * f2.w)));
    }
    __syncthreads();

    // Two source points per thread (stride TPB keeps loads coalesced).
    const int ia = bx * SRC_PER_CTA + tid;
    const int ib = ia + TPB;
    const float* spa = src + ((size_t)b * NPTS + ia) * 3;
    const float* spb = src + ((size_t)b * NPTS + ib) * 3;
    const float ax = spa[0], ay = spa[1], az = spa[2];
    const float bx_ = spb[0], by_ = spb[1], bz_ = spb[2];
    const float qax = -2.0f * ax, qay = -2.0f * ay, qaz = -2.0f * az;
    const float qbx = -2.0f * bx_, qby = -2.0f * by_, qbz = -2.0f * bz_;
    const float npa = fmaf(ax, ax, fmaf(ay, ay, az * az));
    const float npb = fmaf(bx_, bx_, fmaf(by_, by_, bz_ * bz_));

    float ma0 = FLT_MAX, ma1 = FLT_MAX, ma2 = FLT_MAX, ma3 = FLT_MAX;
    float mb0 = FLT_MAX, mb1 = FLT_MAX, mb2 = FLT_MAX, mb3 = FLT_MAX;

    #pragma unroll 2
    for (int j = 0; j < NPTS; j += 8) {
        float4 g0 = sdst[j + 0];
        float4 g1 = sdst[j + 1];
        float4 g2 = sdst[j + 2];
        float4 g3 = sdst[j + 3];
        float4 g4 = sdst[j + 4];
        float4 g5 = sdst[j + 5];
        float4 g6 = sdst[j + 6];
        float4 g7 = sdst[j + 7];

        float da0 = fmaf(qax, g0.x, fmaf(qay, g0.y, fmaf(qaz, g0.z, g0.w)));
        float db0 = fmaf(qbx, g0.x, fmaf(qby, g0.y, fmaf(qbz, g0.z, g0.w)));
        float da1 = fmaf(qax, g1.x, fmaf(qay, g1.y, fmaf(qaz, g1.z, g1.w)));
        float db1 = fmaf(qbx, g1.x, fmaf(qby, g1.y, fmaf(qbz, g1.z, g1.w)));
        float da2 = fmaf(qax, g2.x, fmaf(qay, g2.y, fmaf(qaz, g2.z, g2.w)));
        float db2 = fmaf(qbx, g2.x, fmaf(qby, g2.y, fmaf(qbz, g2.z, g2.w)));
        float da3 = fmaf(qax, g3.x, fmaf(qay, g3.y, fmaf(qaz, g3.z, g3.w)));
        float db3 = fmaf(qbx, g3.x, fmaf(qby, g3.y, fmaf(qbz, g3.z, g3.w)));
        float da4 = fmaf(qax, g4.x, fmaf(qay, g4.y, fmaf(qaz, g4.z, g4.w)));
        float db4 = fmaf(qbx, g4.x, fmaf(qby, g4.y, fmaf(qbz, g4.z, g4.w)));
        float da5 = fmaf(qax, g5.x, fmaf(qay, g5.y, fmaf(qaz, g5.z, g5.w)));
        float db5 = fmaf(qbx, g5.x, fmaf(qby, g5.y, fmaf(qbz, g5.z, g5.w)));
        float da6 = fmaf(qax, g6.x, fmaf(qay, g6.y, fmaf(qaz, g6.z, g6.w)));
        float db6 = fmaf(qbx, g6.x, fmaf(qby, g6.y, fmaf(qbz, g6.z, g6.w)));
        float da7 = fmaf(qax, g7.x, fmaf(qay, g7.y, fmaf(qaz, g7.z, g7.w)));
        float db7 = fmaf(qbx, g7.x, fmaf(qby, g7.y, fmaf(qbz, g7.z, g7.w)));

        ma0 = fminf(ma0, da0);  mb0 = fminf(mb0, db0);
        ma1 = fminf(ma1, da1);  mb1 = fminf(mb1, db1);
        ma2 = fminf(ma2, da2);  mb2 = fminf(mb2, db2);
        ma3 = fminf(ma3, da3);  mb3 = fminf(mb3, db3);
        ma0 = fminf(ma0, da4);  mb0 = fminf(mb0, db4);
        ma1 = fminf(ma1, da5);  mb1 = fminf(mb1, db5);
        ma2 = fminf(ma2, da6);  mb2 = fminf(mb2, db6);
        ma3 = fminf(ma3, da7);  mb3 = fminf(mb3, db7);
    }

    float ma = fminf(fminf(ma0, ma1), fminf(ma2, ma3)) + npa;
    float mb = fminf(fminf(mb0, mb1), fminf(mb2, mb3)) + npb;
    float m = ma + mb;   // thread's contribution to the sum

    // Deterministic block sum (fixed-order tree), reusing smem.
    __syncthreads();
    float* sred = (float*)sdst;
    sred[tid] = m;
    __syncthreads();
    #pragma unroll
    for (int s = TPB / 2; s > 0; s >>= 1) {
        if (tid < s) sred[tid] += sred[tid + s];
        __syncthreads();
    }

    // Publish partial; last CTA finalizes.
    __shared__ unsigned int s_last;
    if (tid == 0) {
        g_partials[bx + CHUNKS * (b + BATCH * dir)] = sred[0];
        __threadfence();
        unsigned int old = atomicAdd(&g_count, 1u);
        s_last = (old == NCTAS - 1) ? 1u : 0u;
    }
    __syncthreads();

    if (s_last) {
        __threadfence();
        float v = g_partials[tid];   // NCTAS == TPB == 128
        sred[tid] = v;
        __syncthreads();
        #pragma unroll
        for (int s = TPB / 2; s > 0; s >>= 1) {
            if (tid < s) sred[tid] += sred[tid + s];
            __syncthreads();
        }
        if (tid == 0) {
            out[0] = sred[0] / (float)(2 * BATCH * NPTS);
            g_count = 0;   // reset for next graph replay
        }
    }
}

extern "C" void kernel_launch(void* const* d_in, const int* in_sizes, int n_in,
                              void* d_out, int out_size)
{
    const float* recon = (const float*)d_in[0];
    const float* gt    = (const float*)d_in[1];
    float* out = (float*)d_out;

    const int smem = NPTS * (int)sizeof(float4);  // 64 KB
    cudaFuncSetAttribute(chamfer_fused_kernel,
                         cudaFuncAttributeMaxDynamicSharedMemorySize, smem);

    dim3 grid(CHUNKS, BATCH, 2);
    chamfer_fused_kernel<<<grid, TPB, smem>>>(recon, gt, out);
}

// round 5
// speedup vs baseline: 1.6915x; 1.6915x over previous
#include <cuda_runtime.h>
#include <float.h>

// Chamfer distance, B=4, N=M=4096, D=3 — dst-split for occupancy.
// Each CTA: 256 src points x 1024-dst split (16KB smem) -> partial min per
// src point written to a unique float4 component (no atomics, deterministic).
// Last CTA combines: min over 4 splits, fixed-order sum, divide.
// dist(p,g) = ||p||^2 + ||g||^2 - 2 p.g ; inner: d' = (-2p).g + ||g||^2
// (3 FFMA seeded by precomputed ||g||^2); ||p||^2 added once after the min.

#define BATCH 4
#define NPTS  4096
#define TPB   256
#define NSPLIT 4
#define SPLIT_PTS (NPTS / NSPLIT)        // 1024
#define CHUNKS (NPTS / TPB)              // 16
#define NSLOTS (2 * BATCH * NPTS)        // 32768 src slots
#define NCTAS (CHUNKS * BATCH * 2 * NSPLIT)  // 512

__device__ float4 g_mins[NSLOTS];        // [slot] -> 4 split partial mins
__device__ unsigned int g_count = 0;

__global__ void __launch_bounds__(TPB) chamfer_split_kernel(
    const float* __restrict__ recon,
    const float* __restrict__ gt,
    float* __restrict__ out)
{
    __shared__ float4 sdst[SPLIT_PTS];   // 16 KB

    const int bx    = blockIdx.x;        // src chunk (0..15)
    const int b     = blockIdx.y;        // batch
    const int zz    = blockIdx.z;        // dir * NSPLIT + split
    const int dir   = zz >> 2;
    const int split = zz & 3;
    const int tid   = threadIdx.x;

    const float* src = (dir == 0) ? recon : gt;
    const float* dst = (dir == 0) ? gt : recon;
    const float* dstb = dst + ((size_t)b * NPTS + (size_t)split * SPLIT_PTS) * 3;

    // Prologue: cache this CTA's dst split (+ squared norms). 4 pts/thread.
    {
        const int base = 4 * tid;        // 0..1020
        const float4* gp = (const float4*)(dstb + 3 * base);
        float4 f0 = gp[0];   // x0 y0 z0 x1
        float4 f1 = gp[1];   // y1 z1 x2 y2
        float4 f2 = gp[2];   // z2 x3 y3 z3
        sdst[base + 0] = make_float4(f0.x, f0.y, f0.z,
                                     fmaf(f0.x, f0.x, fmaf(f0.y, f0.y, f0.z * f0.z)));
        sdst[base + 1] = make_float4(f0.w, f1.x, f1.y,
                                     fmaf(f0.w, f0.w, fmaf(f1.x, f1.x, f1.y * f1.y)));
        sdst[base + 2] = make_float4(f1.z, f1.w, f2.x,
                                     fmaf(f1.z, f1.z, fmaf(f1.w, f1.w, f2.x * f2.x)));
        sdst[base + 3] = make_float4(f2.y, f2.z, f2.w,
                                     fmaf(f2.y, f2.y, fmaf(f2.z, f2.z, f2.w * f2.w)));
    }
    __syncthreads();

    // One src point per thread.
    const int i = bx * TPB + tid;
    const float* sp = src + ((size_t)b * NPTS + i) * 3;
    const float px = sp[0], py = sp[1], pz = sp[2];
    const float qx = -2.0f * px, qy = -2.0f * py, qz = -2.0f * pz;
    const float np = fmaf(px, px, fmaf(py, py, pz * pz));

    float m0 = FLT_MAX, m1 = FLT_MAX, m2 = FLT_MAX, m3 = FLT_MAX;

    #pragma unroll 2
    for (int j = 0; j < SPLIT_PTS; j += 8) {
        float4 g0 = sdst[j + 0];
        float4 g1 = sdst[j + 1];
        float4 g2 = sdst[j + 2];
        float4 g3 = sdst[j + 3];
        float4 g4 = sdst[j + 4];
        float4 g5 = sdst[j + 5];
        float4 g6 = sdst[j + 6];
        float4 g7 = sdst[j + 7];

        float d0 = fmaf(qx, g0.x, fmaf(qy, g0.y, fmaf(qz, g0.z, g0.w)));
        float d1 = fmaf(qx, g1.x, fmaf(qy, g1.y, fmaf(qz, g1.z, g1.w)));
        float d2 = fmaf(qx, g2.x, fmaf(qy, g2.y, fmaf(qz, g2.z, g2.w)));
        float d3 = fmaf(qx, g3.x, fmaf(qy, g3.y, fmaf(qz, g3.z, g3.w)));
        float d4 = fmaf(qx, g4.x, fmaf(qy, g4.y, fmaf(qz, g4.z, g4.w)));
        float d5 = fmaf(qx, g5.x, fmaf(qy, g5.y, fmaf(qz, g5.z, g5.w)));
        float d6 = fmaf(qx, g6.x, fmaf(qy, g6.y, fmaf(qz, g6.z, g6.w)));
        float d7 = fmaf(qx, g7.x, fmaf(qy, g7.y, fmaf(qz, g7.z, g7.w)));

        m0 = fminf(m0, d0);
        m1 = fminf(m1, d1);
        m2 = fminf(m2, d2);
        m3 = fminf(m3, d3);
        m0 = fminf(m0, d4);
        m1 = fminf(m1, d5);
        m2 = fminf(m2, d6);
        m3 = fminf(m3, d7);
    }

    const float m = fminf(fminf(m0, m1), fminf(m2, m3)) + np;

    // Unique slot + component: no atomics, deterministic.
    const int slot = (dir * BATCH + b) * NPTS + i;
    ((float*)&g_mins[slot])[split] = m;

    // Elect last CTA for the finalize pass.
    __shared__ unsigned int s_last;
    __threadfence();
    __syncthreads();
    if (tid == 0) {
        unsigned int old = atomicAdd(&g_count, 1u);
        s_last = (old == NCTAS - 1) ? 1u : 0u;
    }
    __syncthreads();

    if (s_last) {
        __threadfence();  // all g_mins writes visible
        // Fixed-order accumulation: thread t sums slots t, t+256, ...
        float acc = 0.0f;
        #pragma unroll 4
        for (int s = tid; s < NSLOTS; s += TPB) {
            float4 v = g_mins[s];
            acc += fminf(fminf(v.x, v.y), fminf(v.z, v.w));
        }
        __shared__ float sred[TPB];
        sred[tid] = acc;
        __syncthreads();
        #pragma unroll
        for (int s = TPB / 2; s > 0; s >>= 1) {
            if (tid < s) sred[tid] += sred[tid + s];
            __syncthreads();
        }
        if (tid == 0) {
            out[0] = sred[0] / (float)NSLOTS;   // == (mean1+mean2)/2
            g_count = 0;                        // reset for next replay
        }
    }
}

extern "C" void kernel_launch(void* const* d_in, const int* in_sizes, int n_in,
                              void* d_out, int out_size)
{
    const float* recon = (const float*)d_in[0];
    const float* gt    = (const float*)d_in[1];
    float* out = (float*)d_out;

    dim3 grid(CHUNKS, BATCH, 2 * NSPLIT);   // 16 x 4 x 8 = 512 CTAs
    chamfer_split_kernel<<<grid, TPB>>>(recon, gt, out);
}

// round 6
// speedup vs baseline: 2.7099x; 1.6021x over previous
#include <cuda_runtime.h>
#include <float.h>

// Chamfer distance, B=4, N=M=4096, D=3.
// Register-tiled: S=4 src points/thread -> one broadcast LDS.128 per dst point
// feeds 4 pairs (12 FFMA). dst split 32 ways (128 pts, 2KB smem) for occupancy
// and wave balance (1024 CTAs ~ 6.9/SM). Split partial mins combined with
// atomicMin on float bits (values >= 0 -> uint order == float order; min is
// exact -> deterministic). Last CTA does fixed-order final sum.

#define BATCH 4
#define NPTS  4096
#define TPB   256
#define SRC_PER_THREAD 4
#define SRC_PER_CTA (TPB * SRC_PER_THREAD)       // 1024
#define CHUNKS (NPTS / SRC_PER_CTA)              // 4
#define NSPLIT 32
#define SPLIT_PTS (NPTS / NSPLIT)                // 128
#define NSLOTS (2 * BATCH * NPTS)                // 32768
#define NCTAS (CHUNKS * BATCH * 2 * NSPLIT)      // 1024

__device__ unsigned int g_minbits[NSLOTS];
__device__ unsigned int g_count = 0;

__global__ void __launch_bounds__(TPB) init_kernel()
{
    const int idx = blockIdx.x * TPB + threadIdx.x;
    if (idx < NSLOTS) g_minbits[idx] = 0x7F7FFFFFu;   // FLT_MAX bits
}

__global__ void __launch_bounds__(TPB) chamfer_kernel(
    const float* __restrict__ recon,
    const float* __restrict__ gt,
    float* __restrict__ out)
{
    __shared__ float4 sdst[SPLIT_PTS];   // 2 KB

    const int bx    = blockIdx.x;        // src chunk (0..3)
    const int b     = blockIdx.y;        // batch
    const int zz    = blockIdx.z;        // dir*NSPLIT + split
    const int dir   = zz >> 5;
    const int split = zz & 31;
    const int tid   = threadIdx.x;

    const float* src = (dir == 0) ? recon : gt;
    const float* dst = (dir == 0) ? gt : recon;
    const float* dstb = dst + ((size_t)b * NPTS + (size_t)split * SPLIT_PTS) * 3;

    // Prologue: cache this split's 128 dst points (+ squared norm).
    if (tid < SPLIT_PTS) {
        float x = dstb[3 * tid + 0];
        float y = dstb[3 * tid + 1];
        float z = dstb[3 * tid + 2];
        sdst[tid] = make_float4(x, y, z, fmaf(x, x, fmaf(y, y, z * z)));
    }
    __syncthreads();

    // Four src points per thread (stride TPB -> coalesced global loads).
    float qx[4], qy[4], qz[4], mn[4];
    const size_t base = (size_t)b * NPTS + bx * SRC_PER_CTA + tid;
    #pragma unroll
    for (int k = 0; k < 4; ++k) {
        const float* sp = src + (base + k * TPB) * 3;
        qx[k] = -2.0f * sp[0];
        qy[k] = -2.0f * sp[1];
        qz[k] = -2.0f * sp[2];
        mn[k] = FLT_MAX;
    }

    #pragma unroll 2
    for (int j = 0; j < SPLIT_PTS; ++j) {
        float4 g = sdst[j];
        #pragma unroll
        for (int k = 0; k < 4; ++k) {
            float d = fmaf(qx[k], g.x, fmaf(qy[k], g.y, fmaf(qz[k], g.z, g.w)));
            mn[k] = fminf(mn[k], d);
        }
    }

    // Fold in ||p||^2 (recovered from q: np = (qx^2+qy^2+qz^2)/4), then
    // combine across splits with exact atomic min on float bits (>= 0).
    const int slot_base = (dir * BATCH + b) * NPTS + bx * SRC_PER_CTA + tid;
    #pragma unroll
    for (int k = 0; k < 4; ++k) {
        float np = 0.25f * fmaf(qx[k], qx[k], fmaf(qy[k], qy[k], qz[k] * qz[k]));
        float m = mn[k] + np;
        atomicMin(&g_minbits[slot_base + k * TPB], __float_as_uint(m));
    }

    // Elect last CTA to finalize.
    __shared__ unsigned int s_last;
    __threadfence();
    __syncthreads();
    if (tid == 0) {
        unsigned int old = atomicAdd(&g_count, 1u);
        s_last = (old == NCTAS - 1) ? 1u : 0u;
    }
    __syncthreads();

    if (s_last) {
        __threadfence();   // all atomics visible
        float acc = 0.0f;
        const uint4* mv = (const uint4*)g_minbits;
        #pragma unroll 4
        for (int s = tid; s < NSLOTS / 4; s += TPB) {
            uint4 v = mv[s];
            acc += __uint_as_float(v.x) + __uint_as_float(v.y)
                 + __uint_as_float(v.z) + __uint_as_float(v.w);
        }
        __shared__ float sred[TPB];
        sred[tid] = acc;
        __syncthreads();
        #pragma unroll
        for (int s = TPB / 2; s > 0; s >>= 1) {
            if (tid < s) sred[tid] += sred[tid + s];
            __syncthreads();
        }
        if (tid == 0) {
            out[0] = sred[0] / (float)NSLOTS;   // == (mean1 + mean2) / 2
            g_count = 0;                        // reset for next replay
        }
    }
}

extern "C" void kernel_launch(void* const* d_in, const int* in_sizes, int n_in,
                              void* d_out, int out_size)
{
    const float* recon = (const float*)d_in[0];
    const float* gt    = (const float*)d_in[1];
    float* out = (float*)d_out;

    init_kernel<<<NSLOTS / TPB, TPB>>>();

    dim3 grid(CHUNKS, BATCH, 2 * NSPLIT);   // 4 x 4 x 64 = 1024 CTAs
    chamfer_kernel<<<grid, TPB>>>(recon, gt, out);
}

// round 7
// speedup vs baseline: 2.9098x; 1.0738x over previous
#include <cuda_runtime.h>
#include <float.h>

// Chamfer distance, B=4, N=M=4096, D=3.
// R6 structure (dst-split 32x, S=4 src/thread, atomicMin combine) with the
// inner loop converted to packed fma.rn.f32x2: evaluates 2 dst points per
// packed op. Shared layout: per dst pair j, sdst[2j]={x0|x1, y0|y1},
// sdst[2j+1]={z0|z1, w0|w1} (w=||g||^2). q vectors packed once per thread.
// d' = (-2p).g + ||g||^2 ; ||p||^2 folded in before the atomic (dist >= 0
// so float bits compare as uint -> atomicMin exact & deterministic).

#define BATCH 4
#define NPTS  4096
#define TPB   256
#define SRC_PER_THREAD 4
#define SRC_PER_CTA (TPB * SRC_PER_THREAD)       // 1024
#define CHUNKS (NPTS / SRC_PER_CTA)              // 4
#define NSPLIT 32
#define SPLIT_PTS (NPTS / NSPLIT)                // 128
#define SPLIT_PAIRS (SPLIT_PTS / 2)              // 64
#define NSLOTS (2 * BATCH * NPTS)                // 32768
#define NCTAS (CHUNKS * BATCH * 2 * NSPLIT)      // 1024

__device__ unsigned int g_minbits[NSLOTS];
__device__ unsigned int g_count = 0;

typedef unsigned long long u64;

__device__ __forceinline__ u64 pk(float a, float b) {
    u64 r;
    asm("mov.b64 %0, {%1, %2};" : "=l"(r) : "f"(a), "f"(b));
    return r;
}
__device__ __forceinline__ void upk(u64 v, float& lo, float& hi) {
    asm("mov.b64 {%0, %1}, %2;" : "=f"(lo), "=f"(hi) : "l"(v));
}
__device__ __forceinline__ u64 fma2(u64 a, u64 b, u64 c) {
    u64 d;
    asm("fma.rn.f32x2 %0, %1, %2, %3;" : "=l"(d) : "l"(a), "l"(b), "l"(c));
    return d;
}

__global__ void __launch_bounds__(TPB) init_kernel()
{
    const int idx = blockIdx.x * TPB + threadIdx.x;
    if (idx < NSLOTS) g_minbits[idx] = 0x7F7FFFFFu;   // FLT_MAX bits
}

__global__ void __launch_bounds__(TPB) chamfer_kernel(
    const float* __restrict__ recon,
    const float* __restrict__ gt,
    float* __restrict__ out)
{
    __shared__ ulonglong2 sdst[SPLIT_PTS];   // 2 KB (2 entries per dst pair)

    const int bx    = blockIdx.x;        // src chunk (0..3)
    const int b     = blockIdx.y;        // batch
    const int zz    = blockIdx.z;        // dir*NSPLIT + split
    const int dir   = zz >> 5;
    const int split = zz & 31;
    const int tid   = threadIdx.x;

    const float* src = (dir == 0) ? recon : gt;
    const float* dst = (dir == 0) ? gt : recon;
    const float* dstb = dst + ((size_t)b * NPTS + (size_t)split * SPLIT_PTS) * 3;

    // Prologue: threads 0..63 each pack one dst pair (+ squared norms).
    if (tid < SPLIT_PAIRS) {
        const float* g0 = dstb + 6 * tid;
        float x0 = g0[0], y0 = g0[1], z0 = g0[2];
        float x1 = g0[3], y1 = g0[4], z1 = g0[5];
        float w0 = fmaf(x0, x0, fmaf(y0, y0, z0 * z0));
        float w1 = fmaf(x1, x1, fmaf(y1, y1, z1 * z1));
        sdst[2 * tid + 0] = make_ulonglong2(pk(x0, x1), pk(y0, y1));
        sdst[2 * tid + 1] = make_ulonglong2(pk(z0, z1), pk(w0, w1));
    }
    __syncthreads();

    // Four src points per thread; q vectors packed (same value both halves).
    u64 qx[4], qy[4], qz[4];
    float npv[4];
    const size_t base = (size_t)b * NPTS + bx * SRC_PER_CTA + tid;
    #pragma unroll
    for (int k = 0; k < 4; ++k) {
        const float* sp = src + (base + k * TPB) * 3;
        float px = sp[0], py = sp[1], pz = sp[2];
        qx[k] = pk(-2.0f * px, -2.0f * px);
        qy[k] = pk(-2.0f * py, -2.0f * py);
        qz[k] = pk(-2.0f * pz, -2.0f * pz);
        npv[k] = fmaf(px, px, fmaf(py, py, pz * pz));
    }

    float mlo0 = FLT_MAX, mhi0 = FLT_MAX;
    float mlo1 = FLT_MAX, mhi1 = FLT_MAX;
    float mlo2 = FLT_MAX, mhi2 = FLT_MAX;
    float mlo3 = FLT_MAX, mhi3 = FLT_MAX;

    #pragma unroll 4
    for (int j = 0; j < SPLIT_PAIRS; ++j) {
        ulonglong2 A = sdst[2 * j];       // {xx, yy}
        ulonglong2 B = sdst[2 * j + 1];   // {zz, ww}

        u64 d0 = fma2(qx[0], A.x, fma2(qy[0], A.y, fma2(qz[0], B.x, B.y)));
        u64 d1 = fma2(qx[1], A.x, fma2(qy[1], A.y, fma2(qz[1], B.x, B.y)));
        u64 d2 = fma2(qx[2], A.x, fma2(qy[2], A.y, fma2(qz[2], B.x, B.y)));
        u64 d3 = fma2(qx[3], A.x, fma2(qy[3], A.y, fma2(qz[3], B.x, B.y)));

        float lo, hi;
        upk(d0, lo, hi); mlo0 = fminf(mlo0, lo); mhi0 = fminf(mhi0, hi);
        upk(d1, lo, hi); mlo1 = fminf(mlo1, lo); mhi1 = fminf(mhi1, hi);
        upk(d2, lo, hi); mlo2 = fminf(mlo2, lo); mhi2 = fminf(mhi2, hi);
        upk(d3, lo, hi); mlo3 = fminf(mlo3, lo); mhi3 = fminf(mhi3, hi);
    }

    float mn[4];
    mn[0] = fminf(mlo0, mhi0);
    mn[1] = fminf(mlo1, mhi1);
    mn[2] = fminf(mlo2, mhi2);
    mn[3] = fminf(mlo3, mhi3);

    const int slot_base = (dir * BATCH + b) * NPTS + bx * SRC_PER_CTA + tid;
    #pragma unroll
    for (int k = 0; k < 4; ++k) {
        float m = mn[k] + npv[k];
        atomicMin(&g_minbits[slot_base + k * TPB], __float_as_uint(m));
    }

    // Elect last CTA to finalize.
    __shared__ unsigned int s_last;
    __threadfence();
    __syncthreads();
    if (tid == 0) {
        unsigned int old = atomicAdd(&g_count, 1u);
        s_last = (old == NCTAS - 1) ? 1u : 0u;
    }
    __syncthreads();

    if (s_last) {
        __threadfence();   // all atomics visible
        float acc = 0.0f;
        const uint4* mv = (const uint4*)g_minbits;
        #pragma unroll 4
        for (int s = tid; s < NSLOTS / 4; s += TPB) {
            uint4 v = mv[s];
            acc += __uint_as_float(v.x) + __uint_as_float(v.y)
                 + __uint_as_float(v.z) + __uint_as_float(v.w);
        }
        __shared__ float sred[TPB];
        sred[tid] = acc;
        __syncthreads();
        #pragma unroll
        for (int s = TPB / 2; s > 0; s >>= 1) {
            if (tid < s) sred[tid] += sred[tid + s];
            __syncthreads();
        }
        if (tid == 0) {
            out[0] = sred[0] / (float)NSLOTS;   // == (mean1 + mean2) / 2
            g_count = 0;                        // reset for next replay
        }
    }
}

extern "C" void kernel_launch(void* const* d_in, const int* in_sizes, int n_in,
                              void* d_out, int out_size)
{
    const float* recon = (const float*)d_in[0];
    const float* gt    = (const float*)d_in[1];
    float* out = (float*)d_out;

    init_kernel<<<NSLOTS / TPB, TPB>>>();

    dim3 grid(CHUNKS, BATCH, 2 * NSPLIT);   // 4 x 4 x 64 = 1024 CTAs
    chamfer_kernel<<<grid, TPB>>>(recon, gt, out);
}